// round 14
// baseline (speedup 1.0000x reference)
#include <cuda_runtime.h>
#include <cuda_fp16.h>
#include <cstdint>

// ---------------------------------------------------------------------------
// GRU cell fused kernel, base sm_100 target (no tcgen05 in this toolchain).
// fp16 m16n8k16 HMMA, fp32 accumulate, ldmatrix.x4 fragment loads.
// Round-14: R13 (KC=128, NSTG=2, 512thr) + fills interleaved into the
// k-step loop + strength-reduced fill addressing.
//
// gi = x@Wih^T + b_ih ; gh = h@Whh^T + b_hh
// r = sig(gi_r+gh_r); z = sig(gi_z+gh_z); n = tanh(gi_n + r*gh_n)
// h' = (1-z)*n + z*h
// CTA tile M=128 x N=64; 4 fp32 accumulator sets (r, z, gi_n, gh_n).
// ---------------------------------------------------------------------------

#define HID   1024
#define BATCH 16384
#define TM    128
#define TN    64
#define KC    128                     // K halves staged per stage
#define LDSH  136                     // smem row pitch in halves (272B)
#define LDSB  (LDSH * 2)              // 272
#define A_HALVES     (TM * LDSH)                  // 17408
#define STAGE_HALVES ((TM + 3 * TN) * LDSH)       // 320*136 = 43520
#define STAGE_BYTES  (STAGE_HALVES * 2)           // 87040
#define SMEM_TOTAL (2 * STAGE_BYTES)              // 174080
#define TOT_STAGES 16                 // 2 phases * (1024/128)
#define NTHREADS 512

// fp16 operand scratch
__device__ __half g_x  [(size_t)BATCH * HID];
__device__ __half g_h  [(size_t)BATCH * HID];
__device__ __half g_wih[(size_t)3 * HID * HID];
__device__ __half g_whh[(size_t)3 * HID * HID];

static __device__ __forceinline__ uint32_t smem_u32(const void* p) {
    uint32_t a;
    asm("{ .reg .u64 t; cvta.to.shared.u64 t, %1; cvt.u32.u64 %0, t; }" : "=r"(a) : "l"(p));
    return a;
}

static __device__ __forceinline__ void cp16(uint32_t saddr, const void* g) {
    asm volatile("cp.async.cg.shared.global [%0], [%1], 16;" :: "r"(saddr), "l"(g));
}

#define CP_COMMIT()  asm volatile("cp.async.commit_group;" ::: "memory")
#define CP_WAIT(N)   asm volatile("cp.async.wait_group %0;" :: "n"(N) : "memory")

#define MMA(C, A, B0, B1)                                                     \
    asm volatile(                                                             \
        "mma.sync.aligned.m16n8k16.row.col.f32.f16.f16.f32 "                  \
        "{%0,%1,%2,%3},{%4,%5,%6,%7},{%8,%9},{%0,%1,%2,%3};"                  \
        : "+f"((C)[0]), "+f"((C)[1]), "+f"((C)[2]), "+f"((C)[3])              \
        : "r"((A)[0]), "r"((A)[1]), "r"((A)[2]), "r"((A)[3]),                 \
          "r"(B0), "r"(B1))

#define LDSM4(R0, R1, R2, R3, ADDR)                                           \
    asm volatile("ldmatrix.sync.aligned.m8n8.x4.shared.b16 {%0,%1,%2,%3}, [%4];" \
                 : "=r"(R0), "=r"(R1), "=r"(R2), "=r"(R3) : "r"(ADDR))

// ---------------------------------------------------------------------------
// single fused pre-pass: fp32 -> fp16 (RNE) for all four operand tensors.
// ---------------------------------------------------------------------------
__global__ void cvt_fp16_all(const float4* __restrict__ x,   __half2* __restrict__ gx,
                             const float4* __restrict__ h,   __half2* __restrict__ gh,
                             const float4* __restrict__ wih, __half2* __restrict__ gwih,
                             const float4* __restrict__ whh, __half2* __restrict__ gwhh)
{
    const int gid = blockIdx.x * blockDim.x + threadIdx.x;
    const int stride = gridDim.x * blockDim.x;
    const int NXH4 = BATCH * HID / 4;
    const int NW4  = 3 * HID * HID / 4;
    for (int i = gid; i < NXH4; i += stride) {
        float4 v = x[i];
        gx[2*i]   = __float22half2_rn(make_float2(v.x, v.y));
        gx[2*i+1] = __float22half2_rn(make_float2(v.z, v.w));
    }
    for (int i = gid; i < NXH4; i += stride) {
        float4 v = h[i];
        gh[2*i]   = __float22half2_rn(make_float2(v.x, v.y));
        gh[2*i+1] = __float22half2_rn(make_float2(v.z, v.w));
    }
    for (int i = gid; i < NW4; i += stride) {
        float4 v = wih[i];
        gwih[2*i]   = __float22half2_rn(make_float2(v.x, v.y));
        gwih[2*i+1] = __float22half2_rn(make_float2(v.z, v.w));
    }
    for (int i = gid; i < NW4; i += stride) {
        float4 v = whh[i];
        gwhh[2*i]   = __float22half2_rn(make_float2(v.x, v.y));
        gwhh[2*i+1] = __float22half2_rn(make_float2(v.z, v.w));
    }
}

__global__ void __launch_bounds__(NTHREADS, 1)
gru_mma_kernel(const float* __restrict__ hprev_f32,
               const float* __restrict__ bih, const float* __restrict__ bhh,
               float* __restrict__ out)
{
    extern __shared__ __align__(128) __half smemh[];
    const uint32_t sbase = smem_u32(smemh);
    const int tid = threadIdx.x;
    const int wid = tid >> 5, lane = tid & 31;
    const int wm = wid >> 2, wn = wid & 3;       // 4x4 warp grid
    const int r4 = lane >> 2, c4 = lane & 3;
    const int j0 = blockIdx.x * TN;
    const int m0 = blockIdx.y * TM;

    // ldmatrix per-lane byte offsets (canonical x4 pattern)
    const uint32_t lrow = (uint32_t)(lane & 15);
    const uint32_t lhi  = (uint32_t)(lane >> 4) * 16u;
    const uint32_t aoff = (uint32_t)(wm * 32 + lrow) * LDSB + lhi;
    const uint32_t boff = (uint32_t)(wn * 16 + lrow) * LDSB + lhi;

    // ---- strength-reduced fill addressing (per-thread bases) ----
    // A: slot i covers row = arow + 32*i (i=0..3), 16B chunk ach
    // B: slot i covers row = arow + 32*i (i=0..5): gate = i>>1, n = arow + 32*(i&1)
    const int arow = tid >> 4;          // 0..31
    const int ach  = tid & 15;          // 0..15
    const __half* aG0x = g_x + (size_t)(m0 + arow) * HID + ach * 8;
    const __half* aG0h = g_h + (size_t)(m0 + arow) * HID + ach * 8;
    const __half* bG0i = g_wih + (size_t)(j0 + arow) * HID + ach * 8;
    const __half* bG0h = g_whh + (size_t)(j0 + arow) * HID + ach * 8;
    const uint32_t aS0 = (uint32_t)(arow * LDSB + ach * 16);
    const uint32_t bS0 = aS0 + (uint32_t)A_HALVES * 2;

    auto fillA = [&](int s) {
        const __half* base = ((s & 8) ? aG0h : aG0x) + (s & 7) * KC;
        const uint32_t sb = sbase + (uint32_t)(s & 1) * STAGE_BYTES + aS0;
        #pragma unroll
        for (int i = 0; i < 4; ++i)
            cp16(sb + (uint32_t)(i * 32 * LDSB), base + (size_t)i * 32 * HID);
    };
    auto fillB = [&](int s, int lo, int hi) {
        const __half* base = ((s & 8) ? bG0h : bG0i) + (s & 7) * KC;
        const uint32_t sb = sbase + (uint32_t)(s & 1) * STAGE_BYTES + bS0;
        #pragma unroll
        for (int i = 0; i < 6; ++i) {
            if (i < lo || i >= hi) continue;
            cp16(sb + (uint32_t)(i * 32 * LDSB),
                 base + (size_t)(i >> 1) * HID * HID + (size_t)(i & 1) * 32 * HID);
        }
    };

    float aR[2][2][4], aZ[2][2][4], aGI[2][2][4], aGH[2][2][4];
    #pragma unroll
    for (int i = 0; i < 2; ++i)
        #pragma unroll
        for (int j = 0; j < 2; ++j)
            #pragma unroll
            for (int k = 0; k < 4; ++k)
                aR[i][j][k] = aZ[i][j][k] = aGI[i][j][k] = aGH[i][j][k] = 0.f;

    fillA(0); fillB(0, 0, 6); CP_COMMIT();

    for (int s = 0; s < TOT_STAGES; ++s) {
        CP_WAIT(0);                 // fill(s) complete
        __syncthreads();            // all warps done reading buffer (s+1)&1

        const uint32_t As_b = sbase + (uint32_t)(s & 1) * STAGE_BYTES;
        const uint32_t abase = As_b + aoff;
        const uint32_t bbase = As_b + (uint32_t)A_HALVES * 2 + boff;
        float (*aN)[2][4] = (s < 8) ? aGI : aGH;
        const bool more = (s + 1 < TOT_STAGES);

        #pragma unroll
        for (int ks = 0; ks < 8; ++ks) {
            const uint32_t kb = ks * 32;      // 16 halves = 32 bytes
            uint32_t a[2][4];
            LDSM4(a[0][0], a[0][1], a[0][2], a[0][3], abase + kb);
            LDSM4(a[1][0], a[1][1], a[1][2], a[1][3], abase + kb + 16u * LDSB);
            #pragma unroll
            for (int g = 0; g < 3; ++g) {
                uint32_t b0, b1, b2, b3;      // b0/b2: nb0 frag, b1/b3: nb1 frag
                LDSM4(b0, b1, b2, b3, bbase + kb + (uint32_t)(g * 64 * LDSB));
                float (*acc)[2][4] = (g == 0) ? aR : (g == 1) ? aZ : aN;
                MMA(acc[0][0], a[0], b0, b2);
                MMA(acc[1][0], a[1], b0, b2);
                MMA(acc[0][1], a[0], b1, b3);
                MMA(acc[1][1], a[1], b1, b3);
            }
            // interleave next-stage fills into early k-steps
            if (ks == 0 && more) fillA(s + 1);
            if (ks == 1 && more) fillB(s + 1, 0, 3);
            if (ks == 2 && more) { fillB(s + 1, 3, 6); CP_COMMIT(); }
        }
    }

    // ---- epilogue: gates + blend, straight from registers ----
    #pragma unroll
    for (int nb = 0; nb < 2; ++nb) {
        const int col = j0 + wn * 16 + nb * 8 + c4 * 2;   // even -> 8B aligned
        const float br0 = bih[col]           + bhh[col];
        const float br1 = bih[col + 1]       + bhh[col + 1];
        const float bz0 = bih[HID + col]     + bhh[HID + col];
        const float bz1 = bih[HID + col + 1] + bhh[HID + col + 1];
        const float2 bgi = *(const float2*)&bih[2 * HID + col];
        const float2 bgh = *(const float2*)&bhh[2 * HID + col];
        #pragma unroll
        for (int mb = 0; mb < 2; ++mb) {
            #pragma unroll
            for (int half = 0; half < 2; ++half) {
                const int row = m0 + wm * 32 + mb * 16 + r4 + half * 8;
                const float2 hp = *(const float2*)&hprev_f32[(size_t)row * HID + col];
                float o[2];
                #pragma unroll
                for (int e = 0; e < 2; ++e) {
                    const int ci = half * 2 + e;
                    float vr = aR [mb][nb][ci] + (e ? br1 : br0);
                    float vz = aZ [mb][nb][ci] + (e ? bz1 : bz0);
                    float gi = aGI[mb][nb][ci] + (e ? bgi.y : bgi.x);
                    float gh = aGH[mb][nb][ci] + (e ? bgh.y : bgh.x);
                    float r = 1.f / (1.f + __expf(-vr));
                    float z = 1.f / (1.f + __expf(-vz));
                    float n = tanhf(fmaf(r, gh, gi));
                    float hpe = e ? hp.y : hp.x;
                    o[e] = fmaf(z, hpe - n, n);
                }
                *(float2*)&out[(size_t)row * HID + col] = make_float2(o[0], o[1]);
            }
        }
    }
}

extern "C" void kernel_launch(void* const* d_in, const int* in_sizes, int n_in,
                              void* d_out, int out_size)
{
    (void)in_sizes; (void)n_in; (void)out_size;
    const float* x   = (const float*)d_in[0];
    const float* h   = (const float*)d_in[1];
    const float* wih = (const float*)d_in[2];
    const float* whh = (const float*)d_in[3];
    const float* bih = (const float*)d_in[4];
    const float* bhh = (const float*)d_in[5];
    float* out = (float*)d_out;

    void *px, *ph, *pwih, *pwhh;
    cudaGetSymbolAddress(&px,   g_x);
    cudaGetSymbolAddress(&ph,   g_h);
    cudaGetSymbolAddress(&pwih, g_wih);
    cudaGetSymbolAddress(&pwhh, g_whh);

    cvt_fp16_all<<<4096, 256>>>((const float4*)x,   (__half2*)px,
                                (const float4*)h,   (__half2*)ph,
                                (const float4*)wih, (__half2*)pwih,
                                (const float4*)whh, (__half2*)pwhh);

    static int smem_set = 0;
    if (!smem_set) {
        cudaFuncSetAttribute(gru_mma_kernel,
                             cudaFuncAttributeMaxDynamicSharedMemorySize, SMEM_TOTAL);
        smem_set = 1;
    }
    dim3 grid(HID / TN, BATCH / TM);   // (16, 128) = 2048 CTAs
    gru_mma_kernel<<<grid, NTHREADS, SMEM_TOTAL>>>(h, bih, bhh, out);
}

// round 15
// speedup vs baseline: 1.0232x; 1.0232x over previous
#include <cuda_runtime.h>
#include <cuda_fp16.h>
#include <cstdint>

// ---------------------------------------------------------------------------
// GRU cell fused kernel, base sm_100 target (no tcgen05 in this toolchain).
// fp16 m16n8k16 HMMA, fp32 accumulate for r/gi_n/gh_n; Round-15 experiment:
// z gate accumulated in f16 (tests half-rate-fp32-accum hypothesis).
// Loop structure = R13 (proven 744us main): KC=128, NSTG=2, 512 thr.
//
// gi = x@Wih^T + b_ih ; gh = h@Whh^T + b_hh
// r = sig(gi_r+gh_r); z = sig(gi_z+gh_z); n = tanh(gi_n + r*gh_n)
// h' = (1-z)*n + z*h
// ---------------------------------------------------------------------------

#define HID   1024
#define BATCH 16384
#define TM    128
#define TN    64
#define KC    128                     // K halves staged per stage
#define LDSH  136                     // smem row pitch in halves (272B)
#define LDSB  (LDSH * 2)              // 272
#define A_HALVES     (TM * LDSH)                  // 17408
#define STAGE_HALVES ((TM + 3 * TN) * LDSH)       // 43520
#define STAGE_BYTES  (STAGE_HALVES * 2)           // 87040
#define SMEM_TOTAL (2 * STAGE_BYTES)              // 174080
#define TOT_STAGES 16                 // 2 phases * (1024/128)
#define NTHREADS 512

// fp16 operand scratch
__device__ __half g_x  [(size_t)BATCH * HID];
__device__ __half g_h  [(size_t)BATCH * HID];
__device__ __half g_wih[(size_t)3 * HID * HID];
__device__ __half g_whh[(size_t)3 * HID * HID];

static __device__ __forceinline__ uint32_t smem_u32(const void* p) {
    uint32_t a;
    asm("{ .reg .u64 t; cvta.to.shared.u64 t, %1; cvt.u32.u64 %0, t; }" : "=r"(a) : "l"(p));
    return a;
}

static __device__ __forceinline__ void cp16(uint32_t saddr, const void* g) {
    asm volatile("cp.async.cg.shared.global [%0], [%1], 16;" :: "r"(saddr), "l"(g));
}

#define CP_COMMIT()  asm volatile("cp.async.commit_group;" ::: "memory")
#define CP_WAIT(N)   asm volatile("cp.async.wait_group %0;" :: "n"(N) : "memory")

// f32-accum HMMA
#define MMA(C, A, B0, B1)                                                     \
    asm volatile(                                                             \
        "mma.sync.aligned.m16n8k16.row.col.f32.f16.f16.f32 "                  \
        "{%0,%1,%2,%3},{%4,%5,%6,%7},{%8,%9},{%0,%1,%2,%3};"                  \
        : "+f"((C)[0]), "+f"((C)[1]), "+f"((C)[2]), "+f"((C)[3])              \
        : "r"((A)[0]), "r"((A)[1]), "r"((A)[2]), "r"((A)[3]),                 \
          "r"(B0), "r"(B1))

// f16-accum HMMA (D/C = 2 b32 regs holding 4 halves)
#define MMAH(C, A, B0, B1)                                                    \
    asm volatile(                                                             \
        "mma.sync.aligned.m16n8k16.row.col.f16.f16.f16.f16 "                  \
        "{%0,%1},{%2,%3,%4,%5},{%6,%7},{%0,%1};"                              \
        : "+r"((C)[0]), "+r"((C)[1])                                          \
        : "r"((A)[0]), "r"((A)[1]), "r"((A)[2]), "r"((A)[3]),                 \
          "r"(B0), "r"(B1))

#define LDSM4(R0, R1, R2, R3, ADDR)                                           \
    asm volatile("ldmatrix.sync.aligned.m8n8.x4.shared.b16 {%0,%1,%2,%3}, [%4];" \
                 : "=r"(R0), "=r"(R1), "=r"(R2), "=r"(R3) : "r"(ADDR))

// ---------------------------------------------------------------------------
// single fused pre-pass: fp32 -> fp16 (RNE) for all four operand tensors.
// ---------------------------------------------------------------------------
__global__ void cvt_fp16_all(const float4* __restrict__ x,   __half2* __restrict__ gx,
                             const float4* __restrict__ h,   __half2* __restrict__ gh,
                             const float4* __restrict__ wih, __half2* __restrict__ gwih,
                             const float4* __restrict__ whh, __half2* __restrict__ gwhh)
{
    const int gid = blockIdx.x * blockDim.x + threadIdx.x;
    const int stride = gridDim.x * blockDim.x;
    const int NXH4 = BATCH * HID / 4;
    const int NW4  = 3 * HID * HID / 4;
    for (int i = gid; i < NXH4; i += stride) {
        float4 v = x[i];
        gx[2*i]   = __float22half2_rn(make_float2(v.x, v.y));
        gx[2*i+1] = __float22half2_rn(make_float2(v.z, v.w));
    }
    for (int i = gid; i < NXH4; i += stride) {
        float4 v = h[i];
        gh[2*i]   = __float22half2_rn(make_float2(v.x, v.y));
        gh[2*i+1] = __float22half2_rn(make_float2(v.z, v.w));
    }
    for (int i = gid; i < NW4; i += stride) {
        float4 v = wih[i];
        gwih[2*i]   = __float22half2_rn(make_float2(v.x, v.y));
        gwih[2*i+1] = __float22half2_rn(make_float2(v.z, v.w));
    }
    for (int i = gid; i < NW4; i += stride) {
        float4 v = whh[i];
        gwhh[2*i]   = __float22half2_rn(make_float2(v.x, v.y));
        gwhh[2*i+1] = __float22half2_rn(make_float2(v.z, v.w));
    }
}

// one stage (K=128 -> 8 k16-steps). r & aN in f32 accum; z in f16 accum.
static __device__ __forceinline__ void stage_compute(
    uint32_t As_b, uint32_t Bs_b, uint32_t aoff, uint32_t boff,
    float (&aR)[2][2][4], uint32_t (&zF)[2][2][2], float (&aN)[2][2][4])
{
    const uint32_t abase = As_b + aoff;
    const uint32_t bbase = Bs_b + boff;
    #pragma unroll
    for (int ks = 0; ks < 8; ++ks) {
        const uint32_t kb = ks * 32;          // 16 halves = 32 bytes
        uint32_t a[2][4];
        LDSM4(a[0][0], a[0][1], a[0][2], a[0][3], abase + kb);
        LDSM4(a[1][0], a[1][1], a[1][2], a[1][3], abase + kb + 16u * LDSB);
        {   // gate 0 -> r (f32 accum)
            uint32_t b0, b1, b2, b3;
            LDSM4(b0, b1, b2, b3, bbase + kb);
            MMA(aR[0][0], a[0], b0, b2);
            MMA(aR[1][0], a[1], b0, b2);
            MMA(aR[0][1], a[0], b1, b3);
            MMA(aR[1][1], a[1], b1, b3);
        }
        {   // gate 1 -> z (f16 accum)
            uint32_t b0, b1, b2, b3;
            LDSM4(b0, b1, b2, b3, bbase + kb + (uint32_t)(64 * LDSB));
            MMAH(zF[0][0], a[0], b0, b2);
            MMAH(zF[1][0], a[1], b0, b2);
            MMAH(zF[0][1], a[0], b1, b3);
            MMAH(zF[1][1], a[1], b1, b3);
        }
        {   // gate 2 -> gi_n / gh_n (f32 accum)
            uint32_t b0, b1, b2, b3;
            LDSM4(b0, b1, b2, b3, bbase + kb + (uint32_t)(128 * LDSB));
            MMA(aN[0][0], a[0], b0, b2);
            MMA(aN[1][0], a[1], b0, b2);
            MMA(aN[0][1], a[0], b1, b3);
            MMA(aN[1][1], a[1], b1, b3);
        }
    }
}

__global__ void __launch_bounds__(NTHREADS, 1)
gru_mma_kernel(const float* __restrict__ hprev_f32,
               const float* __restrict__ bih, const float* __restrict__ bhh,
               float* __restrict__ out)
{
    extern __shared__ __align__(128) __half smemh[];
    const uint32_t sbase = smem_u32(smemh);
    const int tid = threadIdx.x;
    const int wid = tid >> 5, lane = tid & 31;
    const int wm = wid >> 2, wn = wid & 3;       // 4x4 warp grid
    const int r4 = lane >> 2, c4 = lane & 3;
    const int j0 = blockIdx.x * TN;
    const int m0 = blockIdx.y * TM;

    // ldmatrix per-lane byte offsets (canonical x4 pattern)
    const uint32_t lrow = (uint32_t)(lane & 15);
    const uint32_t lhi  = (uint32_t)(lane >> 4) * 16u;
    const uint32_t aoff = (uint32_t)(wm * 32 + lrow) * LDSB + lhi;
    const uint32_t boff = (uint32_t)(wn * 16 + lrow) * LDSB + lhi;

    float aR[2][2][4], aGI[2][2][4], aGH[2][2][4];
    uint32_t zF[2][2][2];
    #pragma unroll
    for (int i = 0; i < 2; ++i)
        #pragma unroll
        for (int j = 0; j < 2; ++j) {
            #pragma unroll
            for (int k = 0; k < 4; ++k)
                aR[i][j][k] = aGI[i][j][k] = aGH[i][j][k] = 0.f;
            zF[i][j][0] = zF[i][j][1] = 0u;       // +0,+0 halves
        }

    // stage s: phase = s>>3 (0: x/Wih, 1: h/Whh), K offset = (s&7)*128 halves
    auto fill = [&](int s) {
        const int ph = s >> 3;
        const int kk = (s & 7) * KC;
        const __half* A = ph ? g_h : g_x;
        const __half* W = ph ? g_whh : g_wih;
        const uint32_t sb = sbase + (uint32_t)(s & 1) * STAGE_BYTES;
        #pragma unroll
        for (int i = 0; i < 4; ++i) {           // A: 128 rows x 16 16B-chunks
            int idx = tid + (i << 9);
            int row = idx >> 4, ch = idx & 15;
            cp16(sb + (uint32_t)(row * LDSB + ch * 16),
                 A + (size_t)(m0 + row) * HID + kk + ch * 8);
        }
        const uint32_t bb = sb + A_HALVES * 2;
        #pragma unroll
        for (int i = 0; i < 6; ++i) {           // B: 192 rows x 16 chunks
            int idx = tid + (i << 9);
            int row = idx >> 4, ch = idx & 15;  // row 0..191
            int gate = row >> 6, n = row & 63;
            cp16(bb + (uint32_t)(row * LDSB + ch * 16),
                 W + (size_t)(gate * HID + j0 + n) * HID + kk + ch * 8);
        }
    };

    fill(0); CP_COMMIT();

    for (int s = 0; s < TOT_STAGES; ++s) {
        CP_WAIT(0);                 // fill(s) complete (fill(s+1) not yet issued)
        __syncthreads();            // all warps done reading buffer (s+1)&1
        if (s + 1 < TOT_STAGES) { fill(s + 1); CP_COMMIT(); }

        const uint32_t As_b = sbase + (uint32_t)(s & 1) * STAGE_BYTES;
        const uint32_t Bs_b = As_b + A_HALVES * 2;
        if (s < 8) stage_compute(As_b, Bs_b, aoff, boff, aR, zF, aGI);
        else       stage_compute(As_b, Bs_b, aoff, boff, aR, zF, aGH);
    }

    // ---- epilogue: gates + blend, straight from registers ----
    #pragma unroll
    for (int nb = 0; nb < 2; ++nb) {
        const int col = j0 + wn * 16 + nb * 8 + c4 * 2;   // even -> 8B aligned
        const float br0 = bih[col]           + bhh[col];
        const float br1 = bih[col + 1]       + bhh[col + 1];
        const float bz0 = bih[HID + col]     + bhh[HID + col];
        const float bz1 = bih[HID + col + 1] + bhh[HID + col + 1];
        const float2 bgi = *(const float2*)&bih[2 * HID + col];
        const float2 bgh = *(const float2*)&bhh[2 * HID + col];
        #pragma unroll
        for (int mb = 0; mb < 2; ++mb) {
            // unpack z f16 accumulators: reg0 = (row, col),(row, col+1);
            // reg1 = (row+8, col),(row+8, col+1)
            const float2 fz0 = __half22float2(*reinterpret_cast<__half2*>(&zF[mb][nb][0]));
            const float2 fz1 = __half22float2(*reinterpret_cast<__half2*>(&zF[mb][nb][1]));
            #pragma unroll
            for (int half = 0; half < 2; ++half) {
                const int row = m0 + wm * 32 + mb * 16 + r4 + half * 8;
                const float2 hp = *(const float2*)&hprev_f32[(size_t)row * HID + col];
                float o[2];
                #pragma unroll
                for (int e = 0; e < 2; ++e) {
                    const int ci = half * 2 + e;
                    const float zacc = half ? (e ? fz1.y : fz1.x)
                                            : (e ? fz0.y : fz0.x);
                    float vr = aR [mb][nb][ci] + (e ? br1 : br0);
                    float vz = zacc             + (e ? bz1 : bz0);
                    float gi = aGI[mb][nb][ci] + (e ? bgi.y : bgi.x);
                    float gh = aGH[mb][nb][ci] + (e ? bgh.y : bgh.x);
                    float r = 1.f / (1.f + __expf(-vr));
                    float z = 1.f / (1.f + __expf(-vz));
                    float n = tanhf(fmaf(r, gh, gi));
                    float hpe = e ? hp.y : hp.x;
                    o[e] = fmaf(z, hpe - n, n);
                }
                *(float2*)&out[(size_t)row * HID + col] = make_float2(o[0], o[1]);
            }
        }
    }
}

extern "C" void kernel_launch(void* const* d_in, const int* in_sizes, int n_in,
                              void* d_out, int out_size)
{
    (void)in_sizes; (void)n_in; (void)out_size;
    const float* x   = (const float*)d_in[0];
    const float* h   = (const float*)d_in[1];
    const float* wih = (const float*)d_in[2];
    const float* whh = (const float*)d_in[3];
    const float* bih = (const float*)d_in[4];
    const float* bhh = (const float*)d_in[5];
    float* out = (float*)d_out;

    void *px, *ph, *pwih, *pwhh;
    cudaGetSymbolAddress(&px,   g_x);
    cudaGetSymbolAddress(&ph,   g_h);
    cudaGetSymbolAddress(&pwih, g_wih);
    cudaGetSymbolAddress(&pwhh, g_whh);

    cvt_fp16_all<<<4096, 256>>>((const float4*)x,   (__half2*)px,
                                (const float4*)h,   (__half2*)ph,
                                (const float4*)wih, (__half2*)pwih,
                                (const float4*)whh, (__half2*)pwhh);

    static int smem_set = 0;
    if (!smem_set) {
        cudaFuncSetAttribute(gru_mma_kernel,
                             cudaFuncAttributeMaxDynamicSharedMemorySize, SMEM_TOTAL);
        smem_set = 1;
    }
    dim3 grid(HID / TN, BATCH / TM);   // (16, 128) = 2048 CTAs
    gru_mma_kernel<<<grid, NTHREADS, SMEM_TOTAL>>>(h, bih, bhh, out);
}